// round 1
// baseline (speedup 1.0000x reference)
#include <cuda_runtime.h>

#define BDIM 4096
#define DDIM 1024
#define KSEL 1024
#define MARGIN 0.5f
#define EPSV 1e-6f
#define BIGV 1e6f
#define CEPS (1024.0f * 1e-6f * 1e-6f)   /* D * eps^2 */
#define SCALE (1.0f / (4096.0f * 1024.0f))
#define NBINS 4096

// ---------------- device scratch (static: no allocations allowed) ----------
__device__ float g_dist[(size_t)BDIM * BDIM];
__device__ float g_distT[(size_t)BDIM * BDIM];
__device__ float g_a[BDIM];   // ||x||^2 + 2*eps*sum(x)
__device__ float g_b[BDIM];   // ||y||^2 - 2*eps*sum(y)

// ---------------- small kernels -------------------------------------------
__global__ void zero_out_kernel(float* out) {
    if (threadIdx.x == 0) { out[0] = 0.f; out[1] = 0.f; }
}

__global__ void rowstats_kernel(const float* __restrict__ X,
                                const float* __restrict__ Y) {
    __shared__ float r1s[8], r2s[8];
    int r = blockIdx.x;
    const float* p = (blockIdx.y == 0) ? X : Y;
    p += (size_t)r * DDIM;
    float s1 = 0.f, s2 = 0.f;
    for (int i = threadIdx.x; i < DDIM; i += 256) {
        float v = p[i]; s1 += v; s2 += v * v;
    }
    for (int o = 16; o; o >>= 1) {
        s1 += __shfl_down_sync(0xffffffffu, s1, o);
        s2 += __shfl_down_sync(0xffffffffu, s2, o);
    }
    int lane = threadIdx.x & 31, w = threadIdx.x >> 5;
    if (lane == 0) { r1s[w] = s1; r2s[w] = s2; }
    __syncthreads();
    if (threadIdx.x == 0) {
        s1 = 0.f; s2 = 0.f;
        for (int i = 0; i < 8; i++) { s1 += r1s[i]; s2 += r2s[i]; }
        if (blockIdx.y == 0) g_a[r] = s2 + 2.f * EPSV * s1;
        else                 g_b[r] = s2 - 2.f * EPSV * s1;
    }
}

// ---------------- fp32 SIMT GEMM -> distance matrix -----------------------
// C[i,j] = x_i . y_j ; dist = sqrt(max(a_i + b_j - 2C + CEPS, 0))
// 128x128 tile, BK=8, 256 threads, 8x8 per thread (4+4 split), double buffer.
__global__ __launch_bounds__(256, 2)
void gemm_dist_kernel(const float* __restrict__ X, const float* __restrict__ Y) {
    __shared__ float As[2][8][128];
    __shared__ float Bs[2][8][128];

    const int tid  = threadIdx.x;
    const int m0   = blockIdx.y * 128;
    const int n0   = blockIdx.x * 128;
    const int lrow = tid >> 1;
    const int lk   = (tid & 1) << 2;
    const int tx   = tid & 15;
    const int ty   = tid >> 4;

    const float* xg = X + (size_t)(m0 + lrow) * DDIM + lk;
    const float* yg = Y + (size_t)(n0 + lrow) * DDIM + lk;

    float acc[8][8];
#pragma unroll
    for (int i = 0; i < 8; i++)
#pragma unroll
        for (int j = 0; j < 8; j++) acc[i][j] = 0.f;

    // prologue: load tile 0
    {
        float4 av = *(const float4*)xg;
        float4 bv = *(const float4*)yg;
        As[0][lk + 0][lrow] = av.x; As[0][lk + 1][lrow] = av.y;
        As[0][lk + 2][lrow] = av.z; As[0][lk + 3][lrow] = av.w;
        Bs[0][lk + 0][lrow] = bv.x; Bs[0][lk + 1][lrow] = bv.y;
        Bs[0][lk + 2][lrow] = bv.z; Bs[0][lk + 3][lrow] = bv.w;
    }
    __syncthreads();

    const int NT = DDIM / 8;  // 128
    for (int kt = 0; kt < NT; kt++) {
        int buf = kt & 1;
        float4 av2, bv2;
        if (kt + 1 < NT) {
            av2 = *(const float4*)(xg + (size_t)(kt + 1) * 8);
            bv2 = *(const float4*)(yg + (size_t)(kt + 1) * 8);
        }
#pragma unroll
        for (int k = 0; k < 8; k++) {
            float4 a0 = *(const float4*)&As[buf][k][ty * 4];
            float4 a1 = *(const float4*)&As[buf][k][ty * 4 + 64];
            float4 b0 = *(const float4*)&Bs[buf][k][tx * 4];
            float4 b1 = *(const float4*)&Bs[buf][k][tx * 4 + 64];
            float ar[8] = {a0.x, a0.y, a0.z, a0.w, a1.x, a1.y, a1.z, a1.w};
            float br[8] = {b0.x, b0.y, b0.z, b0.w, b1.x, b1.y, b1.z, b1.w};
#pragma unroll
            for (int i = 0; i < 8; i++)
#pragma unroll
                for (int j = 0; j < 8; j++)
                    acc[i][j] += ar[i] * br[j];
        }
        if (kt + 1 < NT) {
            int nb = buf ^ 1;
            As[nb][lk + 0][lrow] = av2.x; As[nb][lk + 1][lrow] = av2.y;
            As[nb][lk + 2][lrow] = av2.z; As[nb][lk + 3][lrow] = av2.w;
            Bs[nb][lk + 0][lrow] = bv2.x; Bs[nb][lk + 1][lrow] = bv2.y;
            Bs[nb][lk + 2][lrow] = bv2.z; Bs[nb][lk + 3][lrow] = bv2.w;
            __syncthreads();
        }
    }

    // epilogue: distance + store (coalesced-ish float4 stores)
#pragma unroll
    for (int i = 0; i < 8; i++) {
        int row = m0 + ((i < 4) ? (ty * 4 + i) : (ty * 4 + 64 + i - 4));
        float arow = g_a[row] + CEPS;
        float t[8];
#pragma unroll
        for (int j = 0; j < 8; j++) {
            int col = n0 + ((j < 4) ? (tx * 4 + j) : (tx * 4 + 64 + j - 4));
            float sq = arow + g_b[col] - 2.f * acc[i][j];
            t[j] = sqrtf(fmaxf(sq, 0.f));
        }
        float* d0 = g_dist + (size_t)row * BDIM + n0 + tx * 4;
        *(float4*)d0        = make_float4(t[0], t[1], t[2], t[3]);
        *(float4*)(d0 + 64) = make_float4(t[4], t[5], t[6], t[7]);
    }
}

// ---------------- transpose (32x32 tiles) ---------------------------------
__global__ void transpose_kernel() {
    __shared__ float tile[32][33];
    int bx = blockIdx.x * 32, by = blockIdx.y * 32;
    int x = bx + threadIdx.x;
#pragma unroll
    for (int i = threadIdx.y; i < 32; i += 8)
        tile[i][threadIdx.x] = g_dist[(size_t)(by + i) * BDIM + x];
    __syncthreads();
    int x2 = by + threadIdx.x;
#pragma unroll
    for (int i = threadIdx.y; i < 32; i += 8)
        g_distT[(size_t)(bx + i) * BDIM + x2] = tile[threadIdx.x][i];
}

// ---------------- block helpers (512 threads) -----------------------------
__device__ __forceinline__ void block_reduce_if(int& ci, float& sf, int tid,
                                                int* ired, float* fred) {
    for (int o = 16; o; o >>= 1) {
        ci += __shfl_down_sync(0xffffffffu, ci, o);
        sf += __shfl_down_sync(0xffffffffu, sf, o);
    }
    int lane = tid & 31, w = tid >> 5;
    if (lane == 0) { ired[w] = ci; fred[w] = sf; }
    __syncthreads();
    if (tid < 32) {
        int c = (tid < 16) ? ired[tid] : 0;
        float s = (tid < 16) ? fred[tid] : 0.f;
        for (int o = 8; o; o >>= 1) {
            c += __shfl_down_sync(0xffffffffu, c, o);
            s += __shfl_down_sync(0xffffffffu, s, o);
        }
        if (tid == 0) { ired[16] = c; fred[16] = s; }
    }
    __syncthreads();
    ci = ired[16]; sf = fred[16];
    __syncthreads();
}

__device__ __forceinline__ int block_exscan512(int v, int tid, int* sc) {
    int lane = tid & 31, w = tid >> 5;
    int x = v;
    for (int o = 1; o < 32; o <<= 1) {
        int t = __shfl_up_sync(0xffffffffu, x, o);
        if (lane >= o) x += t;
    }
    if (lane == 31) sc[w] = x;
    __syncthreads();
    if (tid < 32) {
        int ws = (tid < 16) ? sc[tid] : 0;
        for (int o = 1; o < 16; o <<= 1) {
            int t = __shfl_up_sync(0xffffffffu, ws, o);
            if (lane >= o) ws += t;
        }
        if (tid < 16) sc[tid] = ws;
    }
    __syncthreads();
    int off = (w > 0) ? sc[w - 1] : 0;
    int r = off + x - v;
    __syncthreads();
    return r;
}

// ---------------- per-row loss with histogram select ----------------------
// For each row: pos = row[r]; thr = margin + pos.
// If count(d<thr) <= K: loss = sum_{d<thr}(thr-d).
// Else: loss = K*thr - sum(K smallest d); k-th smallest located by
// two-level 4096-bin histogram; residual bin width thr/4096^2 ~ 3e-6.
__global__ __launch_bounds__(512)
void loss_kernel(int which, float* __restrict__ out, int oidx) {
    __shared__ float row[BDIM];
    __shared__ int   hist[NBINS];
    __shared__ int   ired[17];
    __shared__ float fred[17];
    __shared__ int   sbin[2];

    const float* dmat = which ? g_distT : g_dist;
    int r   = blockIdx.x;
    int tid = threadIdx.x;

    const float4* src = (const float4*)(dmat + (size_t)r * BDIM);
    float4* rowv = (float4*)row;
    for (int i = tid; i < BDIM / 4; i += 512) rowv[i] = src[i];
    __syncthreads();
    float pos = row[r];
    __syncthreads();
    if (tid == 0) row[r] = BIGV;  // exclude diagonal
    for (int i = tid; i < NBINS; i += 512) hist[i] = 0;
    __syncthreads();

    float thr   = MARGIN + pos;
    float inv_w = (float)NBINS / thr;

    // pass 1: count+relu-sum below thr, and level-1 histogram over [0, thr]
    int cnt = 0; float srelu = 0.f;
    for (int i = tid; i < BDIM; i += 512) {
        float d = row[i];
        if (d < thr) {
            cnt++; srelu += thr - d;
            int bin = (int)(d * inv_w);
            bin = bin > NBINS - 1 ? NBINS - 1 : (bin < 0 ? 0 : bin);
            atomicAdd(&hist[bin], 1);
        }
    }
    int Ctot = cnt; float Stot = srelu;
    block_reduce_if(Ctot, Stot, tid, ired, fred);

    if (Ctot <= KSEL) {  // case A: everything below thr is inside top-k
        if (tid == 0) atomicAdd(&out[oidx], Stot * SCALE);
        return;
    }

    // locate level-1 boundary bin containing rank KSEL
    int base = tid * (NBINS / 512);
    int lsum = 0;
#pragma unroll
    for (int j = 0; j < NBINS / 512; j++) lsum += hist[base + j];
    int pref = block_exscan512(lsum, tid, ired);
    if (pref < KSEL && KSEL <= pref + lsum) {
        int c = pref;
#pragma unroll
        for (int j = 0; j < NBINS / 512; j++) {
            int h = hist[base + j];
            if (c + h >= KSEL) { sbin[0] = base + j; sbin[1] = c; break; }
            c += h;
        }
    }
    __syncthreads();
    int   b1  = sbin[0];
    int   r1  = KSEL - sbin[1];
    float w1  = thr * (1.f / NBINS);
    float lo2 = b1 * w1;
    float inv_w2 = (float)NBINS / w1;

    // level-2 histogram within bin b1
    for (int i = tid; i < NBINS; i += 512) hist[i] = 0;
    __syncthreads();
    for (int i = tid; i < BDIM; i += 512) {
        float d = row[i];
        if (d < thr) {
            int bin = (int)(d * inv_w);
            bin = bin > NBINS - 1 ? NBINS - 1 : (bin < 0 ? 0 : bin);
            if (bin == b1) {
                int sb = (int)((d - lo2) * inv_w2);
                sb = sb > NBINS - 1 ? NBINS - 1 : (sb < 0 ? 0 : sb);
                atomicAdd(&hist[sb], 1);
            }
        }
    }
    __syncthreads();
    int lsum2 = 0;
#pragma unroll
    for (int j = 0; j < NBINS / 512; j++) lsum2 += hist[base + j];
    int pref2 = block_exscan512(lsum2, tid, ired);
    if (pref2 < r1 && r1 <= pref2 + lsum2) {
        int c = pref2;
#pragma unroll
        for (int j = 0; j < NBINS / 512; j++) {
            int h = hist[base + j];
            if (c + h >= r1) { sbin[0] = base + j; break; }
            c += h;
        }
    }
    __syncthreads();
    float tstar = lo2 + sbin[0] * (w1 * (1.f / NBINS));  // lower edge of b2

    // final pass: exact sum below tstar; fill remainder at tstar
    int cl = 0; float sl = 0.f;
    for (int i = tid; i < BDIM; i += 512) {
        float d = row[i];
        if (d < tstar) { cl++; sl += d; }
    }
    block_reduce_if(cl, sl, tid, ired, fred);
    if (tid == 0) {
        float ssel = sl + (float)(KSEL - cl) * tstar;
        float loss = (float)KSEL * thr - ssel;
        atomicAdd(&out[oidx], loss * SCALE);
    }
}

// ---------------- launch ---------------------------------------------------
extern "C" void kernel_launch(void* const* d_in, const int* in_sizes, int n_in,
                              void* d_out, int out_size) {
    const float* x = (const float*)d_in[0];
    const float* y = (const float*)d_in[1];
    float* out = (float*)d_out;

    zero_out_kernel<<<1, 32>>>(out);
    rowstats_kernel<<<dim3(BDIM, 2), 256>>>(x, y);
    gemm_dist_kernel<<<dim3(32, 32), 256>>>(x, y);
    transpose_kernel<<<dim3(128, 128), dim3(32, 8)>>>();
    loss_kernel<<<BDIM, 512>>>(0, out, 0);
    loss_kernel<<<BDIM, 512>>>(1, out, 1);
}

// round 3
// speedup vs baseline: 1.6780x; 1.6780x over previous
#include <cuda_runtime.h>
#include <cstdint>

#define BDIM 4096
#define DDIM 1024
#define KSEL 1024
#define MARGIN 0.5f
#define EPSV 1e-6f
#define BIGV 1e6f
#define CEPS (1024.0f * 1e-6f * 1e-6f)   /* D * eps^2 */
#define SCALE (1.0f / (4096.0f * 1024.0f))
#define NBINS 4096

// ---------------- device scratch (static: no allocations allowed) ----------
__device__ float g_dist[(size_t)BDIM * BDIM];
__device__ float g_distT[(size_t)BDIM * BDIM];
__device__ float g_a[BDIM];   // ||x||^2 + 2*eps*sum(x)
__device__ float g_b[BDIM];   // ||y||^2 - 2*eps*sum(y)

// ---------------- small kernels -------------------------------------------
__global__ void zero_out_kernel(float* out) {
    if (threadIdx.x == 0) { out[0] = 0.f; out[1] = 0.f; }
}

__global__ void rowstats_kernel(const float* __restrict__ X,
                                const float* __restrict__ Y) {
    __shared__ float r1s[8], r2s[8];
    int r = blockIdx.x;
    const float* p = (blockIdx.y == 0) ? X : Y;
    p += (size_t)r * DDIM;
    float s1 = 0.f, s2 = 0.f;
    for (int i = threadIdx.x; i < DDIM; i += 256) {
        float v = p[i]; s1 += v; s2 += v * v;
    }
    for (int o = 16; o; o >>= 1) {
        s1 += __shfl_down_sync(0xffffffffu, s1, o);
        s2 += __shfl_down_sync(0xffffffffu, s2, o);
    }
    int lane = threadIdx.x & 31, w = threadIdx.x >> 5;
    if (lane == 0) { r1s[w] = s1; r2s[w] = s2; }
    __syncthreads();
    if (threadIdx.x == 0) {
        s1 = 0.f; s2 = 0.f;
        for (int i = 0; i < 8; i++) { s1 += r1s[i]; s2 += r2s[i]; }
        if (blockIdx.y == 0) g_a[r] = s2 + 2.f * EPSV * s1;
        else                 g_b[r] = s2 - 2.f * EPSV * s1;
    }
}

// ---------------- tf32 tensor-core GEMM -> distance matrix ----------------
// C[i,j] = x_i . y_j ; dist = sqrt(max(a_i + b_j - 2C + CEPS, 0))
// Block 128x128, BK=16 (two k-slices of 8), 256 threads / 8 warps.
// Warp tile 32x64: 2 m-tiles x 8 n-tiles of mma.m16n8k8.tf32.
// smem layout [s][m][kk][{k,k+4}] makes every fragment read one float2 LDS
// with address linear in lane -> conflict free.

__device__ __forceinline__ float to_tf32(float x) {
    uint32_t r;
    asm("cvt.rna.tf32.f32 %0, %1;" : "=r"(r) : "f"(x));
    return __uint_as_float(r);
}

__device__ __forceinline__ void mma_tf32(float* c, uint32_t a0, uint32_t a1,
                                         uint32_t a2, uint32_t a3,
                                         uint32_t b0, uint32_t b1) {
    asm volatile(
        "mma.sync.aligned.m16n8k8.row.col.f32.tf32.tf32.f32 "
        "{%0,%1,%2,%3}, {%4,%5,%6,%7}, {%8,%9}, {%0,%1,%2,%3};"
        : "+f"(c[0]), "+f"(c[1]), "+f"(c[2]), "+f"(c[3])
        : "r"(a0), "r"(a1), "r"(a2), "r"(a3), "r"(b0), "r"(b1));
}

// S layout: [s][m][kk][half]  (half 0 -> k = 8s+kk, half 1 -> k = 8s+kk+4)
__device__ __forceinline__ void sts_tile(float (*S)[128][4][2], int r,
                                         int cbase, float4 v) {
    int s = cbase >> 3;
    int half = (cbase >> 2) & 1;
    S[s][r][0][half] = to_tf32(v.x);
    S[s][r][1][half] = to_tf32(v.y);
    S[s][r][2][half] = to_tf32(v.z);
    S[s][r][3][half] = to_tf32(v.w);
}

__global__ __launch_bounds__(256, 2)
void gemm_dist_kernel(const float* __restrict__ X, const float* __restrict__ Y) {
    __shared__ float As[2][2][128][4][2];   // [buf][s][m][kk][half]
    __shared__ float Bs[2][2][128][4][2];

    const int tid  = threadIdx.x;
    const int m0   = blockIdx.y * 128;
    const int n0   = blockIdx.x * 128;
    const int lane = tid & 31;
    const int wid  = tid >> 5;
    const int wm   = wid & 3;    // 4 warps over m (32 rows each)
    const int wn   = wid >> 2;   // 2 warps over n (64 cols each)
    const int g    = lane >> 2;  // group 0..7
    const int tg   = lane & 3;   // thread-in-group

    const int lrow  = tid >> 2;          // 0..63
    const int cbase = (tid & 3) << 2;    // 0,4,8,12

    const float* xg = X + (size_t)(m0 + lrow) * DDIM + cbase;
    const float* yg = Y + (size_t)(n0 + lrow) * DDIM + cbase;

    float acc[2][8][4];
#pragma unroll
    for (int mt = 0; mt < 2; mt++)
#pragma unroll
        for (int nt = 0; nt < 8; nt++)
#pragma unroll
            for (int q = 0; q < 4; q++) acc[mt][nt][q] = 0.f;

    // prologue: tile 0 into buffer 0
    {
        float4 va0 = *(const float4*)(xg);
        float4 va1 = *(const float4*)(xg + (size_t)64 * DDIM);
        float4 vb0 = *(const float4*)(yg);
        float4 vb1 = *(const float4*)(yg + (size_t)64 * DDIM);
        sts_tile(As[0], lrow,      cbase, va0);
        sts_tile(As[0], lrow + 64, cbase, va1);
        sts_tile(Bs[0], lrow,      cbase, vb0);
        sts_tile(Bs[0], lrow + 64, cbase, vb1);
    }
    __syncthreads();

    const int NT = DDIM / 16;  // 64 mainloop iters
    for (int kt = 0; kt < NT; kt++) {
        const int buf = kt & 1;
        float4 va0, va1, vb0, vb1;
        if (kt + 1 < NT) {
            const float* xp = xg + (size_t)(kt + 1) * 16;
            const float* yp = yg + (size_t)(kt + 1) * 16;
            va0 = *(const float4*)(xp);
            va1 = *(const float4*)(xp + (size_t)64 * DDIM);
            vb0 = *(const float4*)(yp);
            vb1 = *(const float4*)(yp + (size_t)64 * DDIM);
        }

#pragma unroll
        for (int s = 0; s < 2; s++) {
            uint32_t A0[2], A1[2], A2[2], A3[2];
#pragma unroll
            for (int mt = 0; mt < 2; mt++) {
                int mrow = wm * 32 + mt * 16 + g;
                float2 lo = *(const float2*)&As[buf][s][mrow][tg][0];
                float2 hi = *(const float2*)&As[buf][s][mrow + 8][tg][0];
                A0[mt] = __float_as_uint(lo.x);
                A2[mt] = __float_as_uint(lo.y);
                A1[mt] = __float_as_uint(hi.x);
                A3[mt] = __float_as_uint(hi.y);
            }
#pragma unroll
            for (int nt = 0; nt < 8; nt++) {
                int ncol = wn * 64 + nt * 8 + g;
                float2 bv = *(const float2*)&Bs[buf][s][ncol][tg][0];
                uint32_t B0 = __float_as_uint(bv.x);
                uint32_t B1 = __float_as_uint(bv.y);
                mma_tf32(acc[0][nt], A0[0], A1[0], A2[0], A3[0], B0, B1);
                mma_tf32(acc[1][nt], A0[1], A1[1], A2[1], A3[1], B0, B1);
            }
        }

        if (kt + 1 < NT) {
            const int nb = buf ^ 1;
            sts_tile(As[nb], lrow,      cbase, va0);
            sts_tile(As[nb], lrow + 64, cbase, va1);
            sts_tile(Bs[nb], lrow,      cbase, vb0);
            sts_tile(Bs[nb], lrow + 64, cbase, vb1);
            __syncthreads();
        }
    }

    // epilogue: dist = sqrt(max(a_i + b_j - 2C + ceps, 0)), float2 stores
#pragma unroll
    for (int mt = 0; mt < 2; mt++) {
        int r0 = m0 + wm * 32 + mt * 16 + g;
        float ar0 = g_a[r0] + CEPS;
        float ar1 = g_a[r0 + 8] + CEPS;
#pragma unroll
        for (int nt = 0; nt < 8; nt++) {
            int c = n0 + wn * 64 + nt * 8 + 2 * tg;
            float bc0 = g_b[c];
            float bc1 = g_b[c + 1];
            float* a4 = acc[mt][nt];
            float2 lo, hi;
            lo.x = sqrtf(fmaxf(ar0 + bc0 - 2.f * a4[0], 0.f));
            lo.y = sqrtf(fmaxf(ar0 + bc1 - 2.f * a4[1], 0.f));
            hi.x = sqrtf(fmaxf(ar1 + bc0 - 2.f * a4[2], 0.f));
            hi.y = sqrtf(fmaxf(ar1 + bc1 - 2.f * a4[3], 0.f));
            *(float2*)&g_dist[(size_t)r0 * BDIM + c]       = lo;
            *(float2*)&g_dist[(size_t)(r0 + 8) * BDIM + c] = hi;
        }
    }
}

// ---------------- transpose (32x32 tiles) ---------------------------------
__global__ void transpose_kernel() {
    __shared__ float tile[32][33];
    int bx = blockIdx.x * 32, by = blockIdx.y * 32;
    int x = bx + threadIdx.x;
#pragma unroll
    for (int i = threadIdx.y; i < 32; i += 8)
        tile[i][threadIdx.x] = g_dist[(size_t)(by + i) * BDIM + x];
    __syncthreads();
    int x2 = by + threadIdx.x;
#pragma unroll
    for (int i = threadIdx.y; i < 32; i += 8)
        g_distT[(size_t)(bx + i) * BDIM + x2] = tile[threadIdx.x][i];
}

// ---------------- block helpers (512 threads) -----------------------------
__device__ __forceinline__ void block_reduce_if(int& ci, float& sf, int tid,
                                                int* ired, float* fred) {
    for (int o = 16; o; o >>= 1) {
        ci += __shfl_down_sync(0xffffffffu, ci, o);
        sf += __shfl_down_sync(0xffffffffu, sf, o);
    }
    int lane = tid & 31, w = tid >> 5;
    if (lane == 0) { ired[w] = ci; fred[w] = sf; }
    __syncthreads();
    if (tid < 32) {
        int c = (tid < 16) ? ired[tid] : 0;
        float s = (tid < 16) ? fred[tid] : 0.f;
        for (int o = 8; o; o >>= 1) {
            c += __shfl_down_sync(0xffffffffu, c, o);
            s += __shfl_down_sync(0xffffffffu, s, o);
        }
        if (tid == 0) { ired[16] = c; fred[16] = s; }
    }
    __syncthreads();
    ci = ired[16]; sf = fred[16];
    __syncthreads();
}

__device__ __forceinline__ int block_exscan512(int v, int tid, int* sc) {
    int lane = tid & 31, w = tid >> 5;
    int x = v;
    for (int o = 1; o < 32; o <<= 1) {
        int t = __shfl_up_sync(0xffffffffu, x, o);
        if (lane >= o) x += t;
    }
    if (lane == 31) sc[w] = x;
    __syncthreads();
    if (tid < 32) {
        int ws = (tid < 16) ? sc[tid] : 0;
        for (int o = 1; o < 16; o <<= 1) {
            int t = __shfl_up_sync(0xffffffffu, ws, o);
            if (lane >= o) ws += t;
        }
        if (tid < 16) sc[tid] = ws;
    }
    __syncthreads();
    int off = (w > 0) ? sc[w - 1] : 0;
    int r = off + x - v;
    __syncthreads();
    return r;
}

// ---------------- per-row loss with histogram select ----------------------
__global__ __launch_bounds__(512)
void loss_kernel(int which, float* __restrict__ out, int oidx) {
    __shared__ float row[BDIM];
    __shared__ int   hist[NBINS];
    __shared__ int   ired[17];
    __shared__ float fred[17];
    __shared__ int   sbin[2];

    const float* dmat = which ? g_distT : g_dist;
    int r   = blockIdx.x;
    int tid = threadIdx.x;

    const float4* src = (const float4*)(dmat + (size_t)r * BDIM);
    float4* rowv = (float4*)row;
    for (int i = tid; i < BDIM / 4; i += 512) rowv[i] = src[i];
    __syncthreads();
    float pos = row[r];
    __syncthreads();
    if (tid == 0) row[r] = BIGV;  // exclude diagonal
    for (int i = tid; i < NBINS; i += 512) hist[i] = 0;
    __syncthreads();

    float thr   = MARGIN + pos;
    float inv_w = (float)NBINS / thr;

    int cnt = 0; float srelu = 0.f;
    for (int i = tid; i < BDIM; i += 512) {
        float d = row[i];
        if (d < thr) {
            cnt++; srelu += thr - d;
            int bin = (int)(d * inv_w);
            bin = bin > NBINS - 1 ? NBINS - 1 : (bin < 0 ? 0 : bin);
            atomicAdd(&hist[bin], 1);
        }
    }
    int Ctot = cnt; float Stot = srelu;
    block_reduce_if(Ctot, Stot, tid, ired, fred);

    if (Ctot <= KSEL) {
        if (tid == 0) atomicAdd(&out[oidx], Stot * SCALE);
        return;
    }

    int base = tid * (NBINS / 512);
    int lsum = 0;
#pragma unroll
    for (int j = 0; j < NBINS / 512; j++) lsum += hist[base + j];
    int pref = block_exscan512(lsum, tid, ired);
    if (pref < KSEL && KSEL <= pref + lsum) {
        int c = pref;
#pragma unroll
        for (int j = 0; j < NBINS / 512; j++) {
            int h = hist[base + j];
            if (c + h >= KSEL) { sbin[0] = base + j; sbin[1] = c; break; }
            c += h;
        }
    }
    __syncthreads();
    int   b1  = sbin[0];
    int   r1  = KSEL - sbin[1];
    float w1  = thr * (1.f / NBINS);
    float lo2 = b1 * w1;
    float inv_w2 = (float)NBINS / w1;

    for (int i = tid; i < NBINS; i += 512) hist[i] = 0;
    __syncthreads();
    for (int i = tid; i < BDIM; i += 512) {
        float d = row[i];
        if (d < thr) {
            int bin = (int)(d * inv_w);
            bin = bin > NBINS - 1 ? NBINS - 1 : (bin < 0 ? 0 : bin);
            if (bin == b1) {
                int sb = (int)((d - lo2) * inv_w2);
                sb = sb > NBINS - 1 ? NBINS - 1 : (sb < 0 ? 0 : sb);
                atomicAdd(&hist[sb], 1);
            }
        }
    }
    __syncthreads();
    int lsum2 = 0;
#pragma unroll
    for (int j = 0; j < NBINS / 512; j++) lsum2 += hist[base + j];
    int pref2 = block_exscan512(lsum2, tid, ired);
    if (pref2 < r1 && r1 <= pref2 + lsum2) {
        int c = pref2;
#pragma unroll
        for (int j = 0; j < NBINS / 512; j++) {
            int h = hist[base + j];
            if (c + h >= r1) { sbin[0] = base + j; break; }
            c += h;
        }
    }
    __syncthreads();
    float tstar = lo2 + sbin[0] * (w1 * (1.f / NBINS));

    int cl = 0; float sl = 0.f;
    for (int i = tid; i < BDIM; i += 512) {
        float d = row[i];
        if (d < tstar) { cl++; sl += d; }
    }
    block_reduce_if(cl, sl, tid, ired, fred);
    if (tid == 0) {
        float ssel = sl + (float)(KSEL - cl) * tstar;
        float loss = (float)KSEL * thr - ssel;
        atomicAdd(&out[oidx], loss * SCALE);
    }
}

// ---------------- launch ---------------------------------------------------
extern "C" void kernel_launch(void* const* d_in, const int* in_sizes, int n_in,
                              void* d_out, int out_size) {
    const float* x = (const float*)d_in[0];
    const float* y = (const float*)d_in[1];
    float* out = (float*)d_out;

    zero_out_kernel<<<1, 32>>>(out);
    rowstats_kernel<<<dim3(BDIM, 2), 256>>>(x, y);
    gemm_dist_kernel<<<dim3(32, 32), 256>>>(x, y);
    transpose_kernel<<<dim3(128, 128), dim3(32, 8)>>>();
    loss_kernel<<<BDIM, 512>>>(0, out, 0);
    loss_kernel<<<BDIM, 512>>>(1, out, 1);
}

// round 5
// speedup vs baseline: 2.0189x; 1.2031x over previous
#include <cuda_runtime.h>
#include <cstdint>

#define BDIM 4096
#define DDIM 1024
#define KSEL 1024
#define MARGIN 0.5f
#define EPSV 1e-6f
#define BIGV 1e6f
#define CEPS (1024.0f * 1e-6f * 1e-6f)   /* D * eps^2 */
#define SCALE (1.0f / (4096.0f * 1024.0f))
#define NBINS 4096

// GEMM tiling: block 128x128, BK=32, 128 threads (4 warps of 64x64)
#define GM 128
#define GN 128
#define BK 32
#define NKT (DDIM / BK)              /* 32 */
#define RSB 160                      /* smem row stride bytes (32 fl + pad) */
#define OFF_B (128 * RSB)            /* 20480 */
#define STAGE_B (2 * 128 * RSB)      /* 40960 */
#define GSMEM (2 * STAGE_B)          /* 81920 */
#define CSTR 132                     /* epilogue transpose-stage stride (floats) */

// ---------------- device scratch (static: no allocations allowed) ----------
__device__ float g_dist[(size_t)BDIM * BDIM];
__device__ float g_distT[(size_t)BDIM * BDIM];
__device__ float g_a[BDIM];   // ||x||^2 + 2*eps*sum(x)
__device__ float g_b[BDIM];   // ||y||^2 - 2*eps*sum(y)

// ---------------- helpers --------------------------------------------------
__device__ __forceinline__ uint32_t smem_u32(const void* p) {
    return (uint32_t)__cvta_generic_to_shared(p);
}
__device__ __forceinline__ void cp16(uint32_t dst, const void* src) {
    asm volatile("cp.async.cg.shared.global [%0], [%1], 16;" :: "r"(dst), "l"(src));
}
__device__ __forceinline__ void cp_commit() {
    asm volatile("cp.async.commit_group;" ::: "memory");
}
template <int N> __device__ __forceinline__ void cp_wait() {
    asm volatile("cp.async.wait_group %0;" :: "n"(N) : "memory");
}
__device__ __forceinline__ void mma_tf32(float* c, uint32_t a0, uint32_t a1,
                                         uint32_t a2, uint32_t a3,
                                         uint32_t b0, uint32_t b1) {
    asm volatile(
        "mma.sync.aligned.m16n8k8.row.col.f32.tf32.tf32.f32 "
        "{%0,%1,%2,%3}, {%4,%5,%6,%7}, {%8,%9}, {%0,%1,%2,%3};"
        : "+f"(c[0]), "+f"(c[1]), "+f"(c[2]), "+f"(c[3])
        : "r"(a0), "r"(a1), "r"(a2), "r"(a3), "r"(b0), "r"(b1));
}

// ---------------- small kernels -------------------------------------------
__global__ void zero_out_kernel(float* out) {
    if (threadIdx.x == 0) { out[0] = 0.f; out[1] = 0.f; }
}

__global__ void rowstats_kernel(const float* __restrict__ X,
                                const float* __restrict__ Y) {
    __shared__ float r1s[8], r2s[8];
    int r = blockIdx.x;
    const float* p = (blockIdx.y == 0) ? X : Y;
    p += (size_t)r * DDIM;
    float s1 = 0.f, s2 = 0.f;
    for (int i = threadIdx.x; i < DDIM; i += 256) {
        float v = p[i]; s1 += v; s2 += v * v;
    }
    for (int o = 16; o; o >>= 1) {
        s1 += __shfl_down_sync(0xffffffffu, s1, o);
        s2 += __shfl_down_sync(0xffffffffu, s2, o);
    }
    int lane = threadIdx.x & 31, w = threadIdx.x >> 5;
    if (lane == 0) { r1s[w] = s1; r2s[w] = s2; }
    __syncthreads();
    if (threadIdx.x == 0) {
        s1 = 0.f; s2 = 0.f;
        for (int i = 0; i < 8; i++) { s1 += r1s[i]; s2 += r2s[i]; }
        if (blockIdx.y == 0) g_a[r] = s2 + 2.f * EPSV * s1;
        else                 g_b[r] = s2 - 2.f * EPSV * s1;
    }
}

// ---------------- tf32 mma.sync GEMM + fused transpose --------------------
// C[i,j] = x_i . y_j (tf32-truncated operands, fp32 accum)
// dist = sqrt(max(a_i + b_j - 2C + ceps, 0)); writes g_dist AND g_distT.
// k-permutation: logical fragment pair {tg, tg+4} <-> physical {2tg, 2tg+1}
// applied to BOTH A and B -> dot product unchanged, loads become LDS.64.
__global__ __launch_bounds__(128, 2)
void gemm_dist_kernel(const float* __restrict__ X, const float* __restrict__ Y) {
    extern __shared__ char smem[];
    const uint32_t sb = smem_u32(smem);
    const int tid  = threadIdx.x;
    const int lane = tid & 31, wid = tid >> 5;
    const int wm = wid & 1, wn = wid >> 1;   // 2x2 warp grid, 64x64 each
    const int g  = lane >> 2, tg = lane & 3;
    const int m0 = blockIdx.y * GM, n0 = blockIdx.x * GN;

    float acc[4][8][4];
#pragma unroll
    for (int mt = 0; mt < 4; mt++)
#pragma unroll
        for (int nt = 0; nt < 8; nt++)
#pragma unroll
            for (int q = 0; q < 4; q++) acc[mt][nt][q] = 0.f;

    const float* xb = X + (size_t)m0 * DDIM;
    const float* yb = Y + (size_t)n0 * DDIM;

    // stage loader: A 128x32fl + B 128x32fl, 16B chunks, conflict-free
#define LOAD_STAGE(ST, KT)                                                    \
    {                                                                         \
        uint32_t buf = sb + (uint32_t)(ST) * STAGE_B;                         \
        int col0 = (KT) * BK;                                                 \
        _Pragma("unroll")                                                     \
        for (int i = 0; i < 8; i++) {                                         \
            int idx = tid + i * 128;                                          \
            int m = idx >> 3, c = idx & 7;                                    \
            cp16(buf + m * RSB + c * 16, xb + (size_t)m * DDIM + col0 + c * 4);\
        }                                                                     \
        _Pragma("unroll")                                                     \
        for (int i = 0; i < 8; i++) {                                         \
            int idx = tid + i * 128;                                          \
            int n = idx >> 3, c = idx & 7;                                    \
            cp16(buf + OFF_B + n * RSB + c * 16,                              \
                 yb + (size_t)n * DDIM + col0 + c * 4);                       \
        }                                                                     \
    }

    LOAD_STAGE(0, 0);
    cp_commit();

    for (int kt = 0; kt < NKT; kt++) {
        cp_wait<0>();
        __syncthreads();
        if (kt + 1 < NKT) { LOAD_STAGE((kt + 1) & 1, kt + 1); cp_commit(); }

        const char* abuf = smem + (size_t)(kt & 1) * STAGE_B;
        const char* bbuf = abuf + OFF_B;

#pragma unroll
        for (int s = 0; s < 4; s++) {
            uint32_t A0[4], A1[4], A2[4], A3[4];
#pragma unroll
            for (int mt = 0; mt < 4; mt++) {
                int r = wm * 64 + mt * 16 + g;
                float2 lo = *(const float2*)(abuf + r * RSB + s * 32 + tg * 8);
                float2 hi = *(const float2*)(abuf + (r + 8) * RSB + s * 32 + tg * 8);
                A0[mt] = __float_as_uint(lo.x);
                A2[mt] = __float_as_uint(lo.y);
                A1[mt] = __float_as_uint(hi.x);
                A3[mt] = __float_as_uint(hi.y);
            }
#pragma unroll
            for (int nt = 0; nt < 8; nt++) {
                int n = wn * 64 + nt * 8 + g;
                float2 bv = *(const float2*)(bbuf + n * RSB + s * 32 + tg * 8);
                uint32_t B0 = __float_as_uint(bv.x);
                uint32_t B1 = __float_as_uint(bv.y);
                mma_tf32(acc[0][nt], A0[0], A1[0], A2[0], A3[0], B0, B1);
                mma_tf32(acc[1][nt], A0[1], A1[1], A2[1], A3[1], B0, B1);
                mma_tf32(acc[2][nt], A0[2], A1[2], A2[2], A3[2], B0, B1);
                mma_tf32(acc[3][nt], A0[3], A1[3], A2[3], A3[3], B0, B1);
            }
        }
    }

    // epilogue: distances; direct write to g_dist, smem-staged for g_distT
    __syncthreads();
    float* Csh = (float*)smem;
#pragma unroll
    for (int mt = 0; mt < 4; mt++) {
        int r0 = wm * 64 + mt * 16 + g;
        float a0 = g_a[m0 + r0] + CEPS;
        float a1 = g_a[m0 + r0 + 8] + CEPS;
#pragma unroll
        for (int nt = 0; nt < 8; nt++) {
            int c = wn * 64 + nt * 8 + 2 * tg;
            float b0 = g_b[n0 + c], b1 = g_b[n0 + c + 1];
            float* a4 = acc[mt][nt];
            float o00 = sqrtf(fmaxf(a0 + b0 - 2.f * a4[0], 0.f));
            float o01 = sqrtf(fmaxf(a0 + b1 - 2.f * a4[1], 0.f));
            float o10 = sqrtf(fmaxf(a1 + b0 - 2.f * a4[2], 0.f));
            float o11 = sqrtf(fmaxf(a1 + b1 - 2.f * a4[3], 0.f));
            *(float2*)&g_dist[(size_t)(m0 + r0) * BDIM + n0 + c] =
                make_float2(o00, o01);
            *(float2*)&g_dist[(size_t)(m0 + r0 + 8) * BDIM + n0 + c] =
                make_float2(o10, o11);
            Csh[c * CSTR + r0]           = o00;
            Csh[(c + 1) * CSTR + r0]     = o01;
            Csh[c * CSTR + r0 + 8]       = o10;
            Csh[(c + 1) * CSTR + r0 + 8] = o11;
        }
    }
    __syncthreads();
    // write transposed tile: 128 rows x 32 float4
#pragma unroll
    for (int i = tid; i < 128 * 32; i += 128) {
        int j = i >> 5, q = i & 31;
        float4 v = *(float4*)&Csh[j * CSTR + 4 * q];
        *(float4*)&g_distT[(size_t)(n0 + j) * BDIM + m0 + 4 * q] = v;
    }
}

// ---------------- block helpers (512 threads) -----------------------------
__device__ __forceinline__ void block_reduce_if(int& ci, float& sf, int tid,
                                                int* ired, float* fred) {
    for (int o = 16; o; o >>= 1) {
        ci += __shfl_down_sync(0xffffffffu, ci, o);
        sf += __shfl_down_sync(0xffffffffu, sf, o);
    }
    int lane = tid & 31, w = tid >> 5;
    if (lane == 0) { ired[w] = ci; fred[w] = sf; }
    __syncthreads();
    if (tid < 32) {
        int c = (tid < 16) ? ired[tid] : 0;
        float s = (tid < 16) ? fred[tid] : 0.f;
        for (int o = 8; o; o >>= 1) {
            c += __shfl_down_sync(0xffffffffu, c, o);
            s += __shfl_down_sync(0xffffffffu, s, o);
        }
        if (tid == 0) { ired[16] = c; fred[16] = s; }
    }
    __syncthreads();
    ci = ired[16]; sf = fred[16];
    __syncthreads();
}

__device__ __forceinline__ int block_exscan512(int v, int tid, int* sc) {
    int lane = tid & 31, w = tid >> 5;
    int x = v;
    for (int o = 1; o < 32; o <<= 1) {
        int t = __shfl_up_sync(0xffffffffu, x, o);
        if (lane >= o) x += t;
    }
    if (lane == 31) sc[w] = x;
    __syncthreads();
    if (tid < 32) {
        int ws = (tid < 16) ? sc[tid] : 0;
        for (int o = 1; o < 16; o <<= 1) {
            int t = __shfl_up_sync(0xffffffffu, ws, o);
            if (lane >= o) ws += t;
        }
        if (tid < 16) sc[tid] = ws;
    }
    __syncthreads();
    int off = (w > 0) ? sc[w - 1] : 0;
    int r = off + x - v;
    __syncthreads();
    return r;
}

// ---------------- per-row loss with histogram select ----------------------
__global__ __launch_bounds__(512)
void loss_kernel(int which, float* __restrict__ out, int oidx) {
    __shared__ float row[BDIM];
    __shared__ int   hist[NBINS];
    __shared__ int   ired[17];
    __shared__ float fred[17];
    __shared__ int   sbin[2];

    const float* dmat = which ? g_distT : g_dist;
    int r   = blockIdx.x;
    int tid = threadIdx.x;

    const float4* src = (const float4*)(dmat + (size_t)r * BDIM);
    float4* rowv = (float4*)row;
    for (int i = tid; i < BDIM / 4; i += 512) rowv[i] = src[i];
    __syncthreads();
    float pos = row[r];
    __syncthreads();
    if (tid == 0) row[r] = BIGV;  // exclude diagonal
    for (int i = tid; i < NBINS; i += 512) hist[i] = 0;
    __syncthreads();

    float thr   = MARGIN + pos;
    float inv_w = (float)NBINS / thr;

    int cnt = 0; float srelu = 0.f;
    for (int i = tid; i < BDIM; i += 512) {
        float d = row[i];
        if (d < thr) {
            cnt++; srelu += thr - d;
            int bin = (int)(d * inv_w);
            bin = bin > NBINS - 1 ? NBINS - 1 : (bin < 0 ? 0 : bin);
            atomicAdd(&hist[bin], 1);
        }
    }
    int Ctot = cnt; float Stot = srelu;
    block_reduce_if(Ctot, Stot, tid, ired, fred);

    if (Ctot <= KSEL) {
        if (tid == 0) atomicAdd(&out[oidx], Stot * SCALE);
        return;
    }

    int base = tid * (NBINS / 512);
    int lsum = 0;
#pragma unroll
    for (int j = 0; j < NBINS / 512; j++) lsum += hist[base + j];
    int pref = block_exscan512(lsum, tid, ired);
    if (pref < KSEL && KSEL <= pref + lsum) {
        int c = pref;
#pragma unroll
        for (int j = 0; j < NBINS / 512; j++) {
            int h = hist[base + j];
            if (c + h >= KSEL) { sbin[0] = base + j; sbin[1] = c; break; }
            c += h;
        }
    }
    __syncthreads();
    int   b1  = sbin[0];
    int   r1  = KSEL - sbin[1];
    float w1  = thr * (1.f / NBINS);
    float lo2 = b1 * w1;
    float inv_w2 = (float)NBINS / w1;

    for (int i = tid; i < NBINS; i += 512) hist[i] = 0;
    __syncthreads();
    for (int i = tid; i < BDIM; i += 512) {
        float d = row[i];
        if (d < thr) {
            int bin = (int)(d * inv_w);
            bin = bin > NBINS - 1 ? NBINS - 1 : (bin < 0 ? 0 : bin);
            if (bin == b1) {
                int sb = (int)((d - lo2) * inv_w2);
                sb = sb > NBINS - 1 ? NBINS - 1 : (sb < 0 ? 0 : sb);
                atomicAdd(&hist[sb], 1);
            }
        }
    }
    __syncthreads();
    int lsum2 = 0;
#pragma unroll
    for (int j = 0; j < NBINS / 512; j++) lsum2 += hist[base + j];
    int pref2 = block_exscan512(lsum2, tid, ired);
    if (pref2 < r1 && r1 <= pref2 + lsum2) {
        int c = pref2;
#pragma unroll
        for (int j = 0; j < NBINS / 512; j++) {
            int h = hist[base + j];
            if (c + h >= r1) { sbin[0] = base + j; break; }
            c += h;
        }
    }
    __syncthreads();
    float tstar = lo2 + sbin[0] * (w1 * (1.f / NBINS));

    int cl = 0; float sl = 0.f;
    for (int i = tid; i < BDIM; i += 512) {
        float d = row[i];
        if (d < tstar) { cl++; sl += d; }
    }
    block_reduce_if(cl, sl, tid, ired, fred);
    if (tid == 0) {
        float ssel = sl + (float)(KSEL - cl) * tstar;
        float loss = (float)KSEL * thr - ssel;
        atomicAdd(&out[oidx], loss * SCALE);
    }
}

// ---------------- launch ---------------------------------------------------
extern "C" void kernel_launch(void* const* d_in, const int* in_sizes, int n_in,
                              void* d_out, int out_size) {
    const float* x = (const float*)d_in[0];
    const float* y = (const float*)d_in[1];
    float* out = (float*)d_out;

    cudaFuncSetAttribute(gemm_dist_kernel,
                         cudaFuncAttributeMaxDynamicSharedMemorySize, GSMEM);

    zero_out_kernel<<<1, 32>>>(out);
    rowstats_kernel<<<dim3(BDIM, 2), 256>>>(x, y);
    gemm_dist_kernel<<<dim3(BDIM / GN, BDIM / GM), 128, GSMEM>>>(x, y);
    loss_kernel<<<BDIM, 512>>>(0, out, 0);
    loss_kernel<<<BDIM, 512>>>(1, out, 1);
}